// round 3
// baseline (speedup 1.0000x reference)
#include <cuda_runtime.h>
#include <math.h>

#define NS 2048

// ---- scratch (device globals; no allocation allowed) ----
__device__ float g_S[NS * 9];          // R^T Lq R per site
__device__ float g_R[NS * 9];          // rotation per site
__device__ float g_Lq[NS * 9];         // Lambda_q per site
__device__ float g_Abase[NS * 9];      // Lambda_p + Lambda_o per site
__device__ float g_colpart[32 * NS];   // partial column sums of beta
__device__ float g_Cpart[8 * NS * 9];  // per-j-chunk partials of beta@S

// ---- packed f32x2 helpers (sm_103a) ----
typedef unsigned long long ull;
__device__ __forceinline__ ull pk2(float a, float b) {
    ull r; asm("mov.b64 %0, {%1,%2};" : "=l"(r) : "f"(a), "f"(b)); return r;
}
__device__ __forceinline__ void upk2(ull p, float& a, float& b) {
    asm("mov.b64 {%0,%1}, %2;" : "=f"(a), "=f"(b) : "l"(p));
}
__device__ __forceinline__ ull fma2(ull a, ull b, ull c) {
    ull r; asm("fma.rn.f32x2 %0, %1, %2, %3;" : "=l"(r) : "l"(a), "l"(b), "l"(c)); return r;
}
__device__ __forceinline__ ull mul2(ull a, ull b) {
    ull r; asm("mul.rn.f32x2 %0, %1, %2;" : "=l"(r) : "l"(a), "l"(b)); return r;
}
__device__ __forceinline__ ull add2(ull a, ull b) {
    ull r; asm("add.rn.f32x2 %0, %1, %2;" : "=l"(r) : "l"(a), "l"(b)); return r;
}

// ---- 3x3 helpers ----
__device__ __forceinline__ void inv3(const float* a, float* o) {
    float c00 = a[4] * a[8] - a[5] * a[7];
    float c01 = a[5] * a[6] - a[3] * a[8];
    float c02 = a[3] * a[7] - a[4] * a[6];
    float det = a[0] * c00 + a[1] * c01 + a[2] * c02;
    float id = 1.0f / det;
    o[0] = c00 * id;
    o[1] = (a[2] * a[7] - a[1] * a[8]) * id;
    o[2] = (a[1] * a[5] - a[2] * a[4]) * id;
    o[3] = c01 * id;
    o[4] = (a[0] * a[8] - a[2] * a[6]) * id;
    o[5] = (a[2] * a[3] - a[0] * a[5]) * id;
    o[6] = c02 * id;
    o[7] = (a[1] * a[6] - a[0] * a[7]) * id;
    o[8] = (a[0] * a[4] - a[1] * a[3]) * id;
}

__device__ __forceinline__ void mm3(const float* A, const float* B, float* O) {
#pragma unroll
    for (int r = 0; r < 3; r++)
#pragma unroll
        for (int c = 0; c < 3; c++)
            O[r * 3 + c] = A[r * 3 + 0] * B[0 + c] + A[r * 3 + 1] * B[3 + c] + A[r * 3 + 2] * B[6 + c];
}
__device__ __forceinline__ void mTm3(const float* A, const float* B, float* O) {
#pragma unroll
    for (int r = 0; r < 3; r++)
#pragma unroll
        for (int c = 0; c < 3; c++)
            O[r * 3 + c] = A[0 + r] * B[0 + c] + A[3 + r] * B[3 + c] + A[6 + r] * B[6 + c];
}
__device__ __forceinline__ void mmT3(const float* A, const float* B, float* O) {
#pragma unroll
    for (int r = 0; r < 3; r++)
#pragma unroll
        for (int c = 0; c < 3; c++)
            O[r * 3 + c] = A[r * 3 + 0] * B[c * 3 + 0] + A[r * 3 + 1] * B[c * 3 + 1] + A[r * 3 + 2] * B[c * 3 + 2];
}

__device__ __forceinline__ void rodrigues(float x, float y, float z, float* R) {
    float t2 = x * x + y * y + z * z;
    float A, B;
    if (t2 < 1e-12f) {
        A = 1.0f - t2 * (1.0f / 6.0f);
        B = 0.5f - t2 * (1.0f / 24.0f);
    } else {
        float t = sqrtf(t2);
        A = sinf(t) / t;
        B = (1.0f - cosf(t)) / t2;
    }
    R[0] = 1.0f - B * (y * y + z * z);
    R[1] = -A * z + B * x * y;
    R[2] = A * y + B * x * z;
    R[3] = A * z + B * x * y;
    R[4] = 1.0f - B * (x * x + z * z);
    R[5] = -A * x + B * y * z;
    R[6] = -A * y + B * x * z;
    R[7] = A * x + B * y * z;
    R[8] = 1.0f - B * (x * x + y * y);
}

// ==== K1: blocks 0..31 = beta colsum (DRAM stream first); blocks 32..287 = per-site stats ====
__global__ void __launch_bounds__(256) k1_kernel(
    const float* __restrict__ Sp, const float* __restrict__ Sq,
    const float* __restrict__ phi, const float* __restrict__ mu,
    const float* __restrict__ W, const float* __restrict__ beta) {
    __shared__ float sW0[2048];
    __shared__ float sW1[2048];
    __shared__ float sW2[2048];

    if (blockIdx.x < 32) {
        // ---- colsum: 32 blocks, 64 rows each ----
        const int b = blockIdx.x;
        const int i0 = b * 64;
        const int t = threadIdx.x;
        float4 a0 = make_float4(0.f, 0.f, 0.f, 0.f);
        float4 a1 = make_float4(0.f, 0.f, 0.f, 0.f);
#pragma unroll 4
        for (int i = 0; i < 64; i++) {
            const float4* row = (const float4*)(beta + (size_t)(i0 + i) * NS);
            float4 v0 = row[t];
            float4 v1 = row[t + 256];
            a0.x += v0.x; a0.y += v0.y; a0.z += v0.z; a0.w += v0.w;
            a1.x += v1.x; a1.y += v1.y; a1.z += v1.z; a1.w += v1.w;
        }
        ((float4*)(g_colpart + b * NS))[t] = a0;
        ((float4*)(g_colpart + b * NS))[t + 256] = a1;
        return;
    }

    const int warp = threadIdx.x >> 5;
    const int lane = threadIdx.x & 31;
    const int site = (blockIdx.x - 32) * 8 + warp;

    const float mu0 = mu[site * 3 + 0];
    const float mu1 = mu[site * 3 + 1];
    const float mu2 = mu[site * 3 + 2];
    const ull mu0p = pk2(mu0, mu0), mu1p = pk2(mu1, mu1), mu2p = pk2(mu2, mu2);

    ull Z2 = 0ull, sw0p = 0ull, sw1p = 0ull, sw2p = 0ull;
    ull s00p = 0ull, s01p = 0ull, s02p = 0ull, s11p = 0ull, s12p = 0ull, s22p = 0ull;

    for (int ch = 0; ch < 4; ch++) {
        __syncthreads();
        for (int vv = threadIdx.x; vv < 2048; vv += 256) {
            const float* wp = W + (size_t)(ch * 2048 + vv) * 3;
            sW0[vv] = wp[0];
            sW1[vv] = wp[1];
            sW2[vv] = wp[2];
        }
        __syncthreads();
#pragma unroll 2
        for (int it = 0; it < 16; it++) {
            int v = it * 128 + lane * 4;
            ulonglong2 w0 = *(const ulonglong2*)&sW0[v];
            ulonglong2 w1 = *(const ulonglong2*)&sW1[v];
            ulonglong2 w2 = *(const ulonglong2*)&sW2[v];
#pragma unroll
            for (int h = 0; h < 2; h++) {
                ull w0p = h ? w0.y : w0.x;
                ull w1p = h ? w1.y : w1.x;
                ull w2p = h ? w2.y : w2.x;
                ull l = fma2(mu0p, w0p, fma2(mu1p, w1p, mul2(mu2p, w2p)));
                float l0, l1;
                upk2(l, l0, l1);
                ull ep = pk2(__expf(l0), __expf(l1));
                Z2 = add2(Z2, ep);
                ull t0 = mul2(ep, w0p);
                ull t1 = mul2(ep, w1p);
                ull t2 = mul2(ep, w2p);
                sw0p = add2(sw0p, t0);
                sw1p = add2(sw1p, t1);
                sw2p = add2(sw2p, t2);
                s00p = fma2(t0, w0p, s00p);
                s01p = fma2(t0, w1p, s01p);
                s02p = fma2(t0, w2p, s02p);
                s11p = fma2(t1, w1p, s11p);
                s12p = fma2(t1, w2p, s12p);
                s22p = fma2(t2, w2p, s22p);
            }
        }
    }
    float x, y;
    float Z, sw0, sw1, sw2, s00, s01, s02, s11, s12, s22;
    upk2(Z2, x, y);  Z   = x + y;
    upk2(sw0p, x, y); sw0 = x + y;
    upk2(sw1p, x, y); sw1 = x + y;
    upk2(sw2p, x, y); sw2 = x + y;
    upk2(s00p, x, y); s00 = x + y;
    upk2(s01p, x, y); s01 = x + y;
    upk2(s02p, x, y); s02 = x + y;
    upk2(s11p, x, y); s11 = x + y;
    upk2(s12p, x, y); s12 = x + y;
    upk2(s22p, x, y); s22 = x + y;

#pragma unroll
    for (int off = 16; off; off >>= 1) {
        Z += __shfl_xor_sync(~0u, Z, off);
        sw0 += __shfl_xor_sync(~0u, sw0, off);
        sw1 += __shfl_xor_sync(~0u, sw1, off);
        sw2 += __shfl_xor_sync(~0u, sw2, off);
        s00 += __shfl_xor_sync(~0u, s00, off);
        s01 += __shfl_xor_sync(~0u, s01, off);
        s02 += __shfl_xor_sync(~0u, s02, off);
        s11 += __shfl_xor_sync(~0u, s11, off);
        s12 += __shfl_xor_sync(~0u, s12, off);
        s22 += __shfl_xor_sync(~0u, s22, off);
    }

    if (lane == 0) {
        float Zi = 1.0f / Z;
        float m0 = sw0 * Zi, m1 = sw1 * Zi, m2 = sw2 * Zi;
        float Lo[9];
        Lo[0] = s00 * Zi - m0 * m0 + 1e-6f;
        Lo[1] = s01 * Zi - m0 * m1;
        Lo[2] = s02 * Zi - m0 * m2;
        Lo[3] = Lo[1];
        Lo[4] = s11 * Zi - m1 * m1 + 1e-6f;
        Lo[5] = s12 * Zi - m1 * m2;
        Lo[6] = Lo[2];
        Lo[7] = Lo[5];
        Lo[8] = s22 * Zi - m2 * m2 + 1e-6f;

        float a[9], Lp[9];
#pragma unroll
        for (int k = 0; k < 9; k++) a[k] = Sp[site * 9 + k];
        a[0] += 1e-6f; a[4] += 1e-6f; a[8] += 1e-6f;
        inv3(a, Lp);

        float Lq[9];
#pragma unroll
        for (int k = 0; k < 9; k++) a[k] = Sq[site * 9 + k];
        a[0] += 1e-6f; a[4] += 1e-6f; a[8] += 1e-6f;
        inv3(a, Lq);

        float R[9];
        rodrigues(phi[site * 3 + 0], phi[site * 3 + 1], phi[site * 3 + 2], R);

        float T[9], Smat[9];
        mm3(Lq, R, T);
        mTm3(R, T, Smat);

#pragma unroll
        for (int k = 0; k < 9; k++) {
            g_Abase[site * 9 + k] = Lp[k] + Lo[k];
            g_Lq[site * 9 + k] = Lq[k];
            g_R[site * 9 + k] = R[k];
            g_S[site * 9 + k] = Smat[k];
        }
    }
}

// ==== K2: beta@S GEMM partials ====
// 1024 blocks = 128 row-groups x 8 j-chunks of 256. warp -> 2 rows.
__global__ void __launch_bounds__(256) k2_kernel(const float* __restrict__ beta) {
    __shared__ float sS[9][264];  // padded rows: k stride 264 words -> shifted banks
    const int chunk = blockIdx.x & 7;
    const int rg = blockIdx.x >> 3;
    const int j0 = chunk * 256;
    const int warp = threadIdx.x >> 5;
    const int lane = threadIdx.x & 31;
    const int row0 = rg * 16 + warp * 2;

    // stage S chunk transposed: sS[k][j]
    for (int idx = threadIdx.x; idx < 2304; idx += 256) {
        int j = idx / 9;
        int k = idx - 9 * j;
        sS[k][j] = g_S[(size_t)(j0 + j) * 9 + k];
    }
    __syncthreads();

    const int jj = lane * 8;
    const float* b0p = beta + (size_t)row0 * NS + j0 + jj;
    const float* b1p = b0p + NS;
    ulonglong2 b0 = *(const ulonglong2*)b0p;
    ulonglong2 b0h = *(const ulonglong2*)(b0p + 4);
    ulonglong2 b1 = *(const ulonglong2*)b1p;
    ulonglong2 b1h = *(const ulonglong2*)(b1p + 4);

    float c[2][9];
#pragma unroll
    for (int k = 0; k < 9; k++) {
        ulonglong2 sa = *(const ulonglong2*)&sS[k][jj];
        ulonglong2 sb = *(const ulonglong2*)&sS[k][jj + 4];
        ull a0 = fma2(b0.x, sa.x, mul2(b0.y, sa.y));
        a0 = fma2(b0h.x, sb.x, a0);
        a0 = fma2(b0h.y, sb.y, a0);
        ull a1 = fma2(b1.x, sa.x, mul2(b1.y, sa.y));
        a1 = fma2(b1h.x, sb.x, a1);
        a1 = fma2(b1h.y, sb.y, a1);
        float lo, hi;
        upk2(a0, lo, hi);
        c[0][k] = lo + hi;
        upk2(a1, lo, hi);
        c[1][k] = lo + hi;
    }

#pragma unroll
    for (int r = 0; r < 2; r++)
#pragma unroll
        for (int k = 0; k < 9; k++)
#pragma unroll
            for (int off = 16; off; off >>= 1)
                c[r][k] += __shfl_xor_sync(~0u, c[r][k], off);

    if (lane < 2) {
        const int row = row0 + lane;
#pragma unroll
        for (int k = 0; k < 9; k++)
            g_Cpart[((size_t)chunk * NS + row) * 9 + k] = c[lane][k];
    }
}

// ==== K3: reduce partials, assemble M, inverse, write out ====
__global__ void __launch_bounds__(64) k3_kernel(float* __restrict__ out) {
    const int i = blockIdx.x * 64 + threadIdx.x;

    float C[9];
#pragma unroll
    for (int k = 0; k < 9; k++) C[k] = 0.f;
#pragma unroll
    for (int p = 0; p < 8; p++)
#pragma unroll
        for (int k = 0; k < 9; k++)
            C[k] += g_Cpart[((size_t)p * NS + i) * 9 + k];

    float cs = 0.f;
#pragma unroll
    for (int p = 0; p < 32; p++) cs += g_colpart[p * NS + i];

    float R[9], Lq[9], Ab[9];
#pragma unroll
    for (int k = 0; k < 9; k++) {
        R[k] = g_R[i * 9 + k];
        Lq[k] = g_Lq[i * 9 + k];
        Ab[k] = g_Abase[i * 9 + k];
    }

    float T[9], Min[9];
    mm3(R, C, T);
    mmT3(T, R, Min);

    float M[9];
#pragma unroll
    for (int k = 0; k < 9; k++) M[k] = Ab[k] + Min[k] + cs * Lq[k];

    float Ms[9];
#pragma unroll
    for (int r = 0; r < 3; r++)
#pragma unroll
        for (int cc = 0; cc < 3; cc++)
            Ms[r * 3 + cc] = 0.5f * (M[r * 3 + cc] + M[cc * 3 + r]);

#pragma unroll
    for (int k = 0; k < 9; k++)
        if (!isfinite(Ms[k])) Ms[k] = (k == 0 || k == 4 || k == 8) ? 1.0f : 0.0f;
    Ms[0] += 1e-4f; Ms[4] += 1e-4f; Ms[8] += 1e-4f;

    float Mi[9];
    inv3(Ms, Mi);

#pragma unroll
    for (int k = 0; k < 9; k++) {
        out[i * 9 + k] = Ms[k];
        out[NS * 9 + i * 9 + k] = Mi[k];
    }
}

extern "C" void kernel_launch(void* const* d_in, const int* in_sizes, int n_in,
                              void* d_out, int out_size) {
    const float* Sp = (const float*)d_in[0];
    const float* Sq = (const float*)d_in[1];
    const float* phi = (const float*)d_in[2];
    const float* beta = (const float*)d_in[3];
    const float* mu = (const float*)d_in[4];
    const float* W = (const float*)d_in[5];
    float* out = (float*)d_out;

    k1_kernel<<<288, 256>>>(Sp, Sq, phi, mu, W, beta);
    k2_kernel<<<1024, 256>>>(beta);
    k3_kernel<<<32, 64>>>(out);
}

// round 5
// speedup vs baseline: 1.1020x; 1.1020x over previous
#include <cuda_runtime.h>
#include <math.h>

#define NS 2048

// ---- scratch (device globals) ----
__device__ float g_S[NS * 9];            // R^T Lq R (stride 9, consumed by k2)
__device__ float g_R[NS * 12];           // rotation (stride 12 for float4 reads)
__device__ float g_Lq[NS * 12];          // Lambda_q
__device__ float g_Lp[NS * 12];          // Lambda_p
__device__ float g_sm[4 * NS * 12];      // softmax partials [q][site][10 of 12]
__device__ float g_colT[NS * 32];        // colsum partials transposed [j][b]
__device__ float g_Cpart[8 * NS * 12];   // beta@S partials [chunk][row][9 of 12]

// ---- packed f32x2 helpers ----
typedef unsigned long long ull;
__device__ __forceinline__ ull pk2(float a, float b) {
    ull r; asm("mov.b64 %0, {%1,%2};" : "=l"(r) : "f"(a), "f"(b)); return r;
}
__device__ __forceinline__ void upk2(ull p, float& a, float& b) {
    asm("mov.b64 {%0,%1}, %2;" : "=f"(a), "=f"(b) : "l"(p));
}
__device__ __forceinline__ ull fma2(ull a, ull b, ull c) {
    ull r; asm("fma.rn.f32x2 %0, %1, %2, %3;" : "=l"(r) : "l"(a), "l"(b), "l"(c)); return r;
}
__device__ __forceinline__ ull mul2(ull a, ull b) {
    ull r; asm("mul.rn.f32x2 %0, %1, %2;" : "=l"(r) : "l"(a), "l"(b)); return r;
}
__device__ __forceinline__ ull add2(ull a, ull b) {
    ull r; asm("add.rn.f32x2 %0, %1, %2;" : "=l"(r) : "l"(a), "l"(b)); return r;
}

// ---- 3x3 helpers ----
__device__ __forceinline__ void inv3(const float* a, float* o) {
    float c00 = a[4] * a[8] - a[5] * a[7];
    float c01 = a[5] * a[6] - a[3] * a[8];
    float c02 = a[3] * a[7] - a[4] * a[6];
    float det = a[0] * c00 + a[1] * c01 + a[2] * c02;
    float id = 1.0f / det;
    o[0] = c00 * id;
    o[1] = (a[2] * a[7] - a[1] * a[8]) * id;
    o[2] = (a[1] * a[5] - a[2] * a[4]) * id;
    o[3] = c01 * id;
    o[4] = (a[0] * a[8] - a[2] * a[6]) * id;
    o[5] = (a[2] * a[3] - a[0] * a[5]) * id;
    o[6] = c02 * id;
    o[7] = (a[1] * a[6] - a[0] * a[7]) * id;
    o[8] = (a[0] * a[4] - a[1] * a[3]) * id;
}
__device__ __forceinline__ void mm3(const float* A, const float* B, float* O) {
#pragma unroll
    for (int r = 0; r < 3; r++)
#pragma unroll
        for (int c = 0; c < 3; c++)
            O[r * 3 + c] = A[r * 3 + 0] * B[0 + c] + A[r * 3 + 1] * B[3 + c] + A[r * 3 + 2] * B[6 + c];
}
__device__ __forceinline__ void mTm3(const float* A, const float* B, float* O) {
#pragma unroll
    for (int r = 0; r < 3; r++)
#pragma unroll
        for (int c = 0; c < 3; c++)
            O[r * 3 + c] = A[0 + r] * B[0 + c] + A[3 + r] * B[3 + c] + A[6 + r] * B[6 + c];
}
__device__ __forceinline__ void mmT3(const float* A, const float* B, float* O) {
#pragma unroll
    for (int r = 0; r < 3; r++)
#pragma unroll
        for (int c = 0; c < 3; c++)
            O[r * 3 + c] = A[r * 3 + 0] * B[c * 3 + 0] + A[r * 3 + 1] * B[c * 3 + 1] + A[r * 3 + 2] * B[c * 3 + 2];
}
__device__ __forceinline__ void rodrigues(float x, float y, float z, float* R) {
    float t2 = x * x + y * y + z * z;
    float A, B;
    if (t2 < 1e-12f) {
        A = 1.0f - t2 * (1.0f / 6.0f);
        B = 0.5f - t2 * (1.0f / 24.0f);
    } else {
        float t = sqrtf(t2);
        A = sinf(t) / t;
        B = (1.0f - cosf(t)) / t2;
    }
    R[0] = 1.0f - B * (y * y + z * z);
    R[1] = -A * z + B * x * y;
    R[2] = A * y + B * x * z;
    R[3] = A * z + B * x * y;
    R[4] = 1.0f - B * (x * x + z * z);
    R[5] = -A * x + B * y * z;
    R[6] = -A * y + B * x * z;
    R[7] = A * x + B * y * z;
    R[8] = 1.0f - B * (x * x + y * y);
}

// ==== K1 ====
// blocks 0..31   : beta column-sum partials (transposed write)
// blocks 32..39  : per-site geometry (Lp, Lq, R, S)
// blocks 40..1063: softmax partial stats; b-40 = sitegrp*4 + quarter
__global__ void __launch_bounds__(256) k1_kernel(
    const float* __restrict__ Sp, const float* __restrict__ Sq,
    const float* __restrict__ phi, const float* __restrict__ mu,
    const float* __restrict__ W, const float* __restrict__ beta) {
    __shared__ float sW0[2048];
    __shared__ float sW1[2048];
    __shared__ float sW2[2048];

    if (blockIdx.x < 32) {
        // ---- colsum: 64 rows per block, transposed partial write ----
        const int b = blockIdx.x;
        const int i0 = b * 64;
        const int t = threadIdx.x;
        float4 a0 = make_float4(0.f, 0.f, 0.f, 0.f);
        float4 a1 = make_float4(0.f, 0.f, 0.f, 0.f);
#pragma unroll 4
        for (int i = 0; i < 64; i++) {
            const float4* row = (const float4*)(beta + (size_t)(i0 + i) * NS);
            float4 v0 = row[t];
            float4 v1 = row[t + 256];
            a0.x += v0.x; a0.y += v0.y; a0.z += v0.z; a0.w += v0.w;
            a1.x += v1.x; a1.y += v1.y; a1.z += v1.z; a1.w += v1.w;
        }
        int j0 = t * 4;
        g_colT[(j0 + 0) * 32 + b] = a0.x;
        g_colT[(j0 + 1) * 32 + b] = a0.y;
        g_colT[(j0 + 2) * 32 + b] = a0.z;
        g_colT[(j0 + 3) * 32 + b] = a0.w;
        g_colT[(j0 + 1024) * 32 + b] = a1.x;
        g_colT[(j0 + 1025) * 32 + b] = a1.y;
        g_colT[(j0 + 1026) * 32 + b] = a1.z;
        g_colT[(j0 + 1027) * 32 + b] = a1.w;
        return;
    }

    if (blockIdx.x < 40) {
        // ---- geometry: one site per thread ----
        const int site = (blockIdx.x - 32) * 256 + threadIdx.x;
        float a[9], Lp[9], Lq[9];
#pragma unroll
        for (int k = 0; k < 9; k++) a[k] = Sp[site * 9 + k];
        a[0] += 1e-6f; a[4] += 1e-6f; a[8] += 1e-6f;
        inv3(a, Lp);
#pragma unroll
        for (int k = 0; k < 9; k++) a[k] = Sq[site * 9 + k];
        a[0] += 1e-6f; a[4] += 1e-6f; a[8] += 1e-6f;
        inv3(a, Lq);

        float R[9];
        rodrigues(phi[site * 3 + 0], phi[site * 3 + 1], phi[site * 3 + 2], R);

        float T[9], Smat[9];
        mm3(Lq, R, T);
        mTm3(R, T, Smat);

#pragma unroll
        for (int k = 0; k < 9; k++) {
            g_S[site * 9 + k] = Smat[k];
            g_R[site * 12 + k] = R[k];
            g_Lq[site * 12 + k] = Lq[k];
            g_Lp[site * 12 + k] = Lp[k];
        }
        return;
    }

    // ---- softmax partial stats ----
    const int b = blockIdx.x - 40;
    const int q = b & 3;
    const int sitegrp = b >> 2;
    const int warp = threadIdx.x >> 5;
    const int lane = threadIdx.x & 31;
    const int site = sitegrp * 8 + warp;

    // stage W quarter q as three planes
    for (int vv = threadIdx.x; vv < 2048; vv += 256) {
        const float* wp = W + (size_t)(q * 2048 + vv) * 3;
        sW0[vv] = wp[0];
        sW1[vv] = wp[1];
        sW2[vv] = wp[2];
    }
    __syncthreads();

    const float mu0 = mu[site * 3 + 0];
    const float mu1 = mu[site * 3 + 1];
    const float mu2 = mu[site * 3 + 2];
    const ull mu0p = pk2(mu0, mu0), mu1p = pk2(mu1, mu1), mu2p = pk2(mu2, mu2);

    ull Z2 = 0ull, sw0p = 0ull, sw1p = 0ull, sw2p = 0ull;
    ull s00p = 0ull, s01p = 0ull, s02p = 0ull, s11p = 0ull, s12p = 0ull, s22p = 0ull;

#pragma unroll 2
    for (int it = 0; it < 16; it++) {
        int v = it * 128 + lane * 4;
        ulonglong2 w0 = *(const ulonglong2*)&sW0[v];
        ulonglong2 w1 = *(const ulonglong2*)&sW1[v];
        ulonglong2 w2 = *(const ulonglong2*)&sW2[v];
#pragma unroll
        for (int h = 0; h < 2; h++) {
            ull w0p = h ? w0.y : w0.x;
            ull w1p = h ? w1.y : w1.x;
            ull w2p = h ? w2.y : w2.x;
            ull l = fma2(mu0p, w0p, fma2(mu1p, w1p, mul2(mu2p, w2p)));
            float l0, l1;
            upk2(l, l0, l1);
            ull ep = pk2(__expf(l0), __expf(l1));
            Z2 = add2(Z2, ep);
            ull t0 = mul2(ep, w0p);
            ull t1 = mul2(ep, w1p);
            ull t2 = mul2(ep, w2p);
            sw0p = add2(sw0p, t0);
            sw1p = add2(sw1p, t1);
            sw2p = add2(sw2p, t2);
            s00p = fma2(t0, w0p, s00p);
            s01p = fma2(t0, w1p, s01p);
            s02p = fma2(t0, w2p, s02p);
            s11p = fma2(t1, w1p, s11p);
            s12p = fma2(t1, w2p, s12p);
            s22p = fma2(t2, w2p, s22p);
        }
    }

    float st[10];
    float x, y;
    upk2(Z2, x, y);   st[0] = x + y;
    upk2(sw0p, x, y); st[1] = x + y;
    upk2(sw1p, x, y); st[2] = x + y;
    upk2(sw2p, x, y); st[3] = x + y;
    upk2(s00p, x, y); st[4] = x + y;
    upk2(s01p, x, y); st[5] = x + y;
    upk2(s02p, x, y); st[6] = x + y;
    upk2(s11p, x, y); st[7] = x + y;
    upk2(s12p, x, y); st[8] = x + y;
    upk2(s22p, x, y); st[9] = x + y;

#pragma unroll
    for (int k = 0; k < 10; k++)
#pragma unroll
        for (int off = 16; off; off >>= 1)
            st[k] += __shfl_xor_sync(~0u, st[k], off);

    if (lane == 0) {
        float* dst = g_sm + ((size_t)q * NS + site) * 12;
#pragma unroll
        for (int k = 0; k < 10; k++) dst[k] = st[k];
    }
}

// ==== K2: beta@S partials. 1024 blocks = 128 row-groups x 8 j-chunks ====
__global__ void __launch_bounds__(256) k2_kernel(const float* __restrict__ beta) {
    __shared__ float sS[9][264];
    const int chunk = blockIdx.x & 7;
    const int rg = blockIdx.x >> 3;
    const int j0 = chunk * 256;
    const int warp = threadIdx.x >> 5;
    const int lane = threadIdx.x & 31;
    const int row0 = rg * 16 + warp * 2;

    // stage S chunk transposed (one j per thread, no integer div)
    {
        int j = threadIdx.x;
        const float* src = g_S + (size_t)(j0 + j) * 9;
#pragma unroll
        for (int k = 0; k < 9; k++) sS[k][j] = src[k];
    }
    __syncthreads();

    const int jj = lane * 8;
    const float* b0p = beta + (size_t)row0 * NS + j0 + jj;
    const float* b1p = b0p + NS;
    ulonglong2 b0 = *(const ulonglong2*)b0p;
    ulonglong2 b0h = *(const ulonglong2*)(b0p + 4);
    ulonglong2 b1 = *(const ulonglong2*)b1p;
    ulonglong2 b1h = *(const ulonglong2*)(b1p + 4);

    float c[2][9];
#pragma unroll
    for (int k = 0; k < 9; k++) {
        ulonglong2 sa = *(const ulonglong2*)&sS[k][jj];
        ulonglong2 sb = *(const ulonglong2*)&sS[k][jj + 4];
        ull a0 = fma2(b0.x, sa.x, mul2(b0.y, sa.y));
        a0 = fma2(b0h.x, sb.x, a0);
        a0 = fma2(b0h.y, sb.y, a0);
        ull a1 = fma2(b1.x, sa.x, mul2(b1.y, sa.y));
        a1 = fma2(b1h.x, sb.x, a1);
        a1 = fma2(b1h.y, sb.y, a1);
        float lo, hi;
        upk2(a0, lo, hi);
        c[0][k] = lo + hi;
        upk2(a1, lo, hi);
        c[1][k] = lo + hi;
    }

#pragma unroll
    for (int r = 0; r < 2; r++)
#pragma unroll
        for (int k = 0; k < 9; k++)
#pragma unroll
            for (int off = 16; off; off >>= 1)
                c[r][k] += __shfl_xor_sync(~0u, c[r][k], off);

    if (lane < 2) {
        const int row = row0 + lane;
        float* dst = g_Cpart + ((size_t)chunk * NS + row) * 12;
#pragma unroll
        for (int k = 0; k < 9; k++) dst[k] = c[lane][k];
    }
}

// ==== K3: reduce everything, assemble M, invert, write out ====
__global__ void __launch_bounds__(32) k3_kernel(float* __restrict__ out) {
    const int i = blockIdx.x * 32 + threadIdx.x;

    // softmax stats: sum 4 quarters
    float st[12];
#pragma unroll
    for (int k = 0; k < 12; k++) st[k] = 0.f;
#pragma unroll
    for (int p = 0; p < 4; p++) {
        const float4* src = (const float4*)(g_sm + ((size_t)p * NS + i) * 12);
        float4 v0 = src[0], v1 = src[1], v2 = src[2];
        st[0] += v0.x; st[1] += v0.y; st[2] += v0.z; st[3] += v0.w;
        st[4] += v1.x; st[5] += v1.y; st[6] += v1.z; st[7] += v1.w;
        st[8] += v2.x; st[9] += v2.y;
    }
    float Zi = 1.0f / st[0];
    float m0 = st[1] * Zi, m1 = st[2] * Zi, m2 = st[3] * Zi;
    float Lo[9];
    Lo[0] = st[4] * Zi - m0 * m0 + 1e-6f;
    Lo[1] = st[5] * Zi - m0 * m1;
    Lo[2] = st[6] * Zi - m0 * m2;
    Lo[3] = Lo[1];
    Lo[4] = st[7] * Zi - m1 * m1 + 1e-6f;
    Lo[5] = st[8] * Zi - m1 * m2;
    Lo[6] = Lo[2];
    Lo[7] = Lo[5];
    Lo[8] = st[9] * Zi - m2 * m2 + 1e-6f;

    // C = sum of beta@S partials
    float C[9];
#pragma unroll
    for (int k = 0; k < 9; k++) C[k] = 0.f;
#pragma unroll
    for (int p = 0; p < 8; p++) {
        const float4* src = (const float4*)(g_Cpart + ((size_t)p * NS + i) * 12);
        float4 v0 = src[0], v1 = src[1], v2 = src[2];
        C[0] += v0.x; C[1] += v0.y; C[2] += v0.z; C[3] += v0.w;
        C[4] += v1.x; C[5] += v1.y; C[6] += v1.z; C[7] += v1.w;
        C[8] += v2.x;
    }

    // colsum
    float cs = 0.f;
    {
        const float4* src = (const float4*)(g_colT + (size_t)i * 32);
#pragma unroll
        for (int p = 0; p < 8; p++) {
            float4 v = src[p];
            cs += v.x + v.y + v.z + v.w;
        }
    }

    float R[9], Lq[9], Ab[9];
    {
        const float4* r4 = (const float4*)(g_R + (size_t)i * 12);
        float4 v0 = r4[0], v1 = r4[1], v2 = r4[2];
        R[0] = v0.x; R[1] = v0.y; R[2] = v0.z; R[3] = v0.w;
        R[4] = v1.x; R[5] = v1.y; R[6] = v1.z; R[7] = v1.w;
        R[8] = v2.x;
        const float4* q4 = (const float4*)(g_Lq + (size_t)i * 12);
        v0 = q4[0]; v1 = q4[1]; v2 = q4[2];
        Lq[0] = v0.x; Lq[1] = v0.y; Lq[2] = v0.z; Lq[3] = v0.w;
        Lq[4] = v1.x; Lq[5] = v1.y; Lq[6] = v1.z; Lq[7] = v1.w;
        Lq[8] = v2.x;
        const float4* p4 = (const float4*)(g_Lp + (size_t)i * 12);
        v0 = p4[0]; v1 = p4[1]; v2 = p4[2];
        Ab[0] = v0.x + Lo[0]; Ab[1] = v0.y + Lo[1]; Ab[2] = v0.z + Lo[2];
        Ab[3] = v0.w + Lo[3]; Ab[4] = v1.x + Lo[4]; Ab[5] = v1.y + Lo[5];
        Ab[6] = v1.z + Lo[6]; Ab[7] = v1.w + Lo[7]; Ab[8] = v2.x + Lo[8];
    }

    float T[9], Min[9];
    mm3(R, C, T);
    mmT3(T, R, Min);

    float M[9];
#pragma unroll
    for (int k = 0; k < 9; k++) M[k] = Ab[k] + Min[k] + cs * Lq[k];

    float Ms[9];
#pragma unroll
    for (int r = 0; r < 3; r++)
#pragma unroll
        for (int cc = 0; cc < 3; cc++)
            Ms[r * 3 + cc] = 0.5f * (M[r * 3 + cc] + M[cc * 3 + r]);

#pragma unroll
    for (int k = 0; k < 9; k++)
        if (!isfinite(Ms[k])) Ms[k] = (k == 0 || k == 4 || k == 8) ? 1.0f : 0.0f;
    Ms[0] += 1e-4f; Ms[4] += 1e-4f; Ms[8] += 1e-4f;

    float Mi[9];
    inv3(Ms, Mi);

#pragma unroll
    for (int k = 0; k < 9; k++) {
        out[i * 9 + k] = Ms[k];
        out[NS * 9 + i * 9 + k] = Mi[k];
    }
}

extern "C" void kernel_launch(void* const* d_in, const int* in_sizes, int n_in,
                              void* d_out, int out_size) {
    const float* Sp = (const float*)d_in[0];
    const float* Sq = (const float*)d_in[1];
    const float* phi = (const float*)d_in[2];
    const float* beta = (const float*)d_in[3];
    const float* mu = (const float*)d_in[4];
    const float* W = (const float*)d_in[5];
    float* out = (float*)d_out;

    k1_kernel<<<1064, 256>>>(Sp, Sq, phi, mu, W, beta);
    k2_kernel<<<1024, 256>>>(beta);
    k3_kernel<<<64, 32>>>(out);
}

// round 7
// speedup vs baseline: 1.1030x; 1.0009x over previous
#include <cuda_runtime.h>
#include <math.h>

#define NS 2048

// ---- scratch (device globals) ----
__device__ float g_R[NS * 12];           // rotation (stride 12 for float4 reads)
__device__ float g_Lq[NS * 12];          // Lambda_q
__device__ float g_Lp[NS * 12];          // Lambda_p
__device__ float g_sm[4 * NS * 12];      // softmax partials [q][site][10 of 12]
__device__ float g_colp[NS * 128];       // colsum partials [j][rg]
__device__ float g_Cpart[8 * NS * 12];   // beta@S partials [chunk][row][9 of 12]

// ---- packed f32x2 helpers ----
typedef unsigned long long ull;
__device__ __forceinline__ ull pk2(float a, float b) {
    ull r; asm("mov.b64 %0, {%1,%2};" : "=l"(r) : "f"(a), "f"(b)); return r;
}
__device__ __forceinline__ void upk2(ull p, float& a, float& b) {
    asm("mov.b64 {%0,%1}, %2;" : "=f"(a), "=f"(b) : "l"(p));
}
__device__ __forceinline__ ull fma2(ull a, ull b, ull c) {
    ull r; asm("fma.rn.f32x2 %0, %1, %2, %3;" : "=l"(r) : "l"(a), "l"(b), "l"(c)); return r;
}
__device__ __forceinline__ ull mul2(ull a, ull b) {
    ull r; asm("mul.rn.f32x2 %0, %1, %2;" : "=l"(r) : "l"(a), "l"(b)); return r;
}
__device__ __forceinline__ ull add2(ull a, ull b) {
    ull r; asm("add.rn.f32x2 %0, %1, %2;" : "=l"(r) : "l"(a), "l"(b)); return r;
}

// ---- 3x3 helpers ----
__device__ __forceinline__ void inv3(const float* a, float* o) {
    float c00 = a[4] * a[8] - a[5] * a[7];
    float c01 = a[5] * a[6] - a[3] * a[8];
    float c02 = a[3] * a[7] - a[4] * a[6];
    float det = a[0] * c00 + a[1] * c01 + a[2] * c02;
    float id = 1.0f / det;
    o[0] = c00 * id;
    o[1] = (a[2] * a[7] - a[1] * a[8]) * id;
    o[2] = (a[1] * a[5] - a[2] * a[4]) * id;
    o[3] = c01 * id;
    o[4] = (a[0] * a[8] - a[2] * a[6]) * id;
    o[5] = (a[2] * a[3] - a[0] * a[5]) * id;
    o[6] = c02 * id;
    o[7] = (a[1] * a[6] - a[0] * a[7]) * id;
    o[8] = (a[0] * a[4] - a[1] * a[3]) * id;
}
__device__ __forceinline__ void mm3(const float* A, const float* B, float* O) {
#pragma unroll
    for (int r = 0; r < 3; r++)
#pragma unroll
        for (int c = 0; c < 3; c++)
            O[r * 3 + c] = A[r * 3 + 0] * B[0 + c] + A[r * 3 + 1] * B[3 + c] + A[r * 3 + 2] * B[6 + c];
}
__device__ __forceinline__ void mTm3(const float* A, const float* B, float* O) {
#pragma unroll
    for (int r = 0; r < 3; r++)
#pragma unroll
        for (int c = 0; c < 3; c++)
            O[r * 3 + c] = A[0 + r] * B[0 + c] + A[3 + r] * B[3 + c] + A[6 + r] * B[6 + c];
}
__device__ __forceinline__ void mmT3(const float* A, const float* B, float* O) {
#pragma unroll
    for (int r = 0; r < 3; r++)
#pragma unroll
        for (int c = 0; c < 3; c++)
            O[r * 3 + c] = A[r * 3 + 0] * B[c * 3 + 0] + A[r * 3 + 1] * B[c * 3 + 1] + A[r * 3 + 2] * B[c * 3 + 2];
}
__device__ __forceinline__ void rodrigues(float x, float y, float z, float* R) {
    float t2 = x * x + y * y + z * z;
    float A, B;
    if (t2 < 1e-12f) {
        A = 1.0f - t2 * (1.0f / 6.0f);
        B = 0.5f - t2 * (1.0f / 24.0f);
    } else {
        float t = sqrtf(t2);
        A = sinf(t) / t;
        B = (1.0f - cosf(t)) / t2;
    }
    R[0] = 1.0f - B * (y * y + z * z);
    R[1] = -A * z + B * x * y;
    R[2] = A * y + B * x * z;
    R[3] = A * z + B * x * y;
    R[4] = 1.0f - B * (x * x + z * z);
    R[5] = -A * x + B * y * z;
    R[6] = -A * y + B * x * z;
    R[7] = A * x + B * y * z;
    R[8] = 1.0f - B * (x * x + y * y);
}

// compute S = R^T inv(Sq+eps) R for one site
__device__ __forceinline__ void site_S(const float* __restrict__ Sq,
                                       const float* __restrict__ phi,
                                       int site, float* Smat) {
    float a[9], Lq[9];
#pragma unroll
    for (int k = 0; k < 9; k++) a[k] = Sq[site * 9 + k];
    a[0] += 1e-6f; a[4] += 1e-6f; a[8] += 1e-6f;
    inv3(a, Lq);
    float R[9];
    rodrigues(phi[site * 3 + 0], phi[site * 3 + 1], phi[site * 3 + 2], R);
    float T[9];
    mm3(Lq, R, T);
    mTm3(R, T, Smat);
}

// ==== MEGA kernel ====
// blocks 0..511    : softmax partial stats (2 sites/warp, quarter split)
// blocks 512..1535 : beta@S GEMM partials + colsum partials (local S)
// blocks 1536..1543: geometry for the final kernel (Lp, Lq, R)
__global__ void __launch_bounds__(256) mega_kernel(
    const float* __restrict__ Sp, const float* __restrict__ Sq,
    const float* __restrict__ phi, const float* __restrict__ mu,
    const float* __restrict__ W, const float* __restrict__ beta) {
    __shared__ float buf[6144];  // softmax: 3 planes of 2048; gemm: sS + scol

    if (blockIdx.x < 512) {
        // ---------------- softmax ----------------
        const int b = blockIdx.x;
        const int q = b & 3;
        const int sg = b >> 2;
        const int warp = threadIdx.x >> 5;
        const int lane = threadIdx.x & 31;
        const int siteA = sg * 16 + warp * 2;
        const int siteB = siteA + 1;

        float* sW0 = buf;
        float* sW1 = buf + 2048;
        float* sW2 = buf + 4096;
        for (int vv = threadIdx.x; vv < 2048; vv += 256) {
            const float* wp = W + (size_t)(q * 2048 + vv) * 3;
            sW0[vv] = wp[0];
            sW1[vv] = wp[1];
            sW2[vv] = wp[2];
        }
        __syncthreads();

        const ull muA0 = pk2(mu[siteA * 3 + 0], mu[siteA * 3 + 0]);
        const ull muA1 = pk2(mu[siteA * 3 + 1], mu[siteA * 3 + 1]);
        const ull muA2 = pk2(mu[siteA * 3 + 2], mu[siteA * 3 + 2]);
        const ull muB0 = pk2(mu[siteB * 3 + 0], mu[siteB * 3 + 0]);
        const ull muB1 = pk2(mu[siteB * 3 + 1], mu[siteB * 3 + 1]);
        const ull muB2 = pk2(mu[siteB * 3 + 2], mu[siteB * 3 + 2]);

        ull aA[10], aB[10];
#pragma unroll
        for (int k = 0; k < 10; k++) { aA[k] = 0ull; aB[k] = 0ull; }

#pragma unroll 4
        for (int it = 0; it < 16; it++) {
            int v = it * 128 + lane * 4;
            ulonglong2 w0 = *(const ulonglong2*)&sW0[v];
            ulonglong2 w1 = *(const ulonglong2*)&sW1[v];
            ulonglong2 w2 = *(const ulonglong2*)&sW2[v];
#pragma unroll
            for (int h = 0; h < 2; h++) {
                ull w0p = h ? w0.y : w0.x;
                ull w1p = h ? w1.y : w1.x;
                ull w2p = h ? w2.y : w2.x;
                ull lA = fma2(muA0, w0p, fma2(muA1, w1p, mul2(muA2, w2p)));
                ull lB = fma2(muB0, w0p, fma2(muB1, w1p, mul2(muB2, w2p)));
                float x0, x1, y0, y1;
                upk2(lA, x0, x1);
                upk2(lB, y0, y1);
                ull eA = pk2(__expf(x0), __expf(x1));
                ull eB = pk2(__expf(y0), __expf(y1));
                ull t0, t1, t2;
                t0 = mul2(eA, w0p); t1 = mul2(eA, w1p); t2 = mul2(eA, w2p);
                aA[0] = add2(aA[0], eA);
                aA[1] = add2(aA[1], t0);
                aA[2] = add2(aA[2], t1);
                aA[3] = add2(aA[3], t2);
                aA[4] = fma2(t0, w0p, aA[4]);
                aA[5] = fma2(t0, w1p, aA[5]);
                aA[6] = fma2(t0, w2p, aA[6]);
                aA[7] = fma2(t1, w1p, aA[7]);
                aA[8] = fma2(t1, w2p, aA[8]);
                aA[9] = fma2(t2, w2p, aA[9]);
                t0 = mul2(eB, w0p); t1 = mul2(eB, w1p); t2 = mul2(eB, w2p);
                aB[0] = add2(aB[0], eB);
                aB[1] = add2(aB[1], t0);
                aB[2] = add2(aB[2], t1);
                aB[3] = add2(aB[3], t2);
                aB[4] = fma2(t0, w0p, aB[4]);
                aB[5] = fma2(t0, w1p, aB[5]);
                aB[6] = fma2(t0, w2p, aB[6]);
                aB[7] = fma2(t1, w1p, aB[7]);
                aB[8] = fma2(t1, w2p, aB[8]);
                aB[9] = fma2(t2, w2p, aB[9]);
            }
        }

        float st[20];
#pragma unroll
        for (int k = 0; k < 10; k++) {
            float lo, hi;
            upk2(aA[k], lo, hi);
            st[k] = lo + hi;
            upk2(aB[k], lo, hi);
            st[10 + k] = lo + hi;
        }
#pragma unroll
        for (int k = 0; k < 20; k++)
#pragma unroll
            for (int off = 16; off; off >>= 1)
                st[k] += __shfl_xor_sync(~0u, st[k], off);

        if (lane < 2) {
            float* dst = g_sm + ((size_t)q * NS + siteA + lane) * 12;
#pragma unroll
            for (int k = 0; k < 10; k++) dst[k] = st[lane * 10 + k];
        }
        return;
    }

    if (blockIdx.x < 1536) {
        // ---------------- GEMM + colsum partials ----------------
        const int t = blockIdx.x - 512;
        const int chunk = t & 7;
        const int rg = t >> 3;
        const int j0 = chunk * 256;
        const int warp = threadIdx.x >> 5;
        const int lane = threadIdx.x & 31;
        const int row0 = rg * 16 + warp * 2;

        float* sS = buf;            // [9][264] -> sS[k*264 + j]
        float* scol = buf + 2400;   // [8][264] -> scol[w*264 + j]

        // local S for this j-chunk (one site per thread)
        {
            float Smat[9];
            site_S(Sq, phi, j0 + threadIdx.x, Smat);
#pragma unroll
            for (int k = 0; k < 9; k++) sS[k * 264 + threadIdx.x] = Smat[k];
        }
        __syncthreads();

        const int jj = lane * 8;
        const float* b0p = beta + (size_t)row0 * NS + j0 + jj;
        const float* b1p = b0p + NS;
        ulonglong2 b0 = *(const ulonglong2*)b0p;
        ulonglong2 b0h = *(const ulonglong2*)(b0p + 4);
        ulonglong2 b1 = *(const ulonglong2*)b1p;
        ulonglong2 b1h = *(const ulonglong2*)(b1p + 4);

        float c[2][9];
#pragma unroll
        for (int k = 0; k < 9; k++) {
            ulonglong2 sa = *(const ulonglong2*)&sS[k * 264 + jj];
            ulonglong2 sb = *(const ulonglong2*)&sS[k * 264 + jj + 4];
            ull a0 = fma2(b0.x, sa.x, mul2(b0.y, sa.y));
            a0 = fma2(b0h.x, sb.x, a0);
            a0 = fma2(b0h.y, sb.y, a0);
            ull a1 = fma2(b1.x, sa.x, mul2(b1.y, sa.y));
            a1 = fma2(b1h.x, sb.x, a1);
            a1 = fma2(b1h.y, sb.y, a1);
            float lo, hi;
            upk2(a0, lo, hi);
            c[0][k] = lo + hi;
            upk2(a1, lo, hi);
            c[1][k] = lo + hi;
        }

        // colsum partial over this block's 2 rows per warp
        {
            ull c0 = add2(b0.x, b1.x);
            ull c1 = add2(b0.y, b1.y);
            ull c2 = add2(b0h.x, b1h.x);
            ull c3 = add2(b0h.y, b1h.y);
            float* dst = scol + warp * 264 + jj;
            float lo, hi;
            upk2(c0, lo, hi); dst[0] = lo; dst[1] = hi;
            upk2(c1, lo, hi); dst[2] = lo; dst[3] = hi;
            upk2(c2, lo, hi); dst[4] = lo; dst[5] = hi;
            upk2(c3, lo, hi); dst[6] = lo; dst[7] = hi;
        }

#pragma unroll
        for (int r = 0; r < 2; r++)
#pragma unroll
            for (int k = 0; k < 9; k++)
#pragma unroll
                for (int off = 16; off; off >>= 1)
                    c[r][k] += __shfl_xor_sync(~0u, c[r][k], off);

        if (lane < 2) {
            const int row = row0 + lane;
            float* dst = g_Cpart + ((size_t)chunk * NS + row) * 12;
#pragma unroll
            for (int k = 0; k < 9; k++) dst[k] = c[lane][k];
        }

        __syncthreads();
        // reduce colsum partials across the 8 warps; thread t -> j = j0 + t
        {
            float s = 0.f;
#pragma unroll
            for (int w = 0; w < 8; w++) s += scol[w * 264 + threadIdx.x];
            g_colp[(size_t)(j0 + threadIdx.x) * 128 + rg] = s;
        }
        return;
    }

    // ---------------- geometry for final kernel ----------------
    {
        const int site = (blockIdx.x - 1536) * 256 + threadIdx.x;
        float a[9], Lp[9], Lq[9];
#pragma unroll
        for (int k = 0; k < 9; k++) a[k] = Sp[site * 9 + k];
        a[0] += 1e-6f; a[4] += 1e-6f; a[8] += 1e-6f;
        inv3(a, Lp);
#pragma unroll
        for (int k = 0; k < 9; k++) a[k] = Sq[site * 9 + k];
        a[0] += 1e-6f; a[4] += 1e-6f; a[8] += 1e-6f;
        inv3(a, Lq);
        float R[9];
        rodrigues(phi[site * 3 + 0], phi[site * 3 + 1], phi[site * 3 + 2], R);
#pragma unroll
        for (int k = 0; k < 9; k++) {
            g_R[site * 12 + k] = R[k];
            g_Lq[site * 12 + k] = Lq[k];
            g_Lp[site * 12 + k] = Lp[k];
        }
    }
}

// ==== FINAL: reduce everything, assemble M, invert, write out ====
__global__ void __launch_bounds__(32) final_kernel(float* __restrict__ out) {
    const int i = blockIdx.x * 32 + threadIdx.x;

    // softmax stats: sum 4 quarters
    float st[12];
#pragma unroll
    for (int k = 0; k < 12; k++) st[k] = 0.f;
#pragma unroll
    for (int p = 0; p < 4; p++) {
        const float4* src = (const float4*)(g_sm + ((size_t)p * NS + i) * 12);
        float4 v0 = src[0], v1 = src[1], v2 = src[2];
        st[0] += v0.x; st[1] += v0.y; st[2] += v0.z; st[3] += v0.w;
        st[4] += v1.x; st[5] += v1.y; st[6] += v1.z; st[7] += v1.w;
        st[8] += v2.x; st[9] += v2.y;
    }
    float Zi = 1.0f / st[0];
    float m0 = st[1] * Zi, m1 = st[2] * Zi, m2 = st[3] * Zi;
    float Lo[9];
    Lo[0] = st[4] * Zi - m0 * m0 + 1e-6f;
    Lo[1] = st[5] * Zi - m0 * m1;
    Lo[2] = st[6] * Zi - m0 * m2;
    Lo[3] = Lo[1];
    Lo[4] = st[7] * Zi - m1 * m1 + 1e-6f;
    Lo[5] = st[8] * Zi - m1 * m2;
    Lo[6] = Lo[2];
    Lo[7] = Lo[5];
    Lo[8] = st[9] * Zi - m2 * m2 + 1e-6f;

    // C = sum of beta@S partials
    float C[9];
#pragma unroll
    for (int k = 0; k < 9; k++) C[k] = 0.f;
#pragma unroll
    for (int p = 0; p < 8; p++) {
        const float4* src = (const float4*)(g_Cpart + ((size_t)p * NS + i) * 12);
        float4 v0 = src[0], v1 = src[1], v2 = src[2];
        C[0] += v0.x; C[1] += v0.y; C[2] += v0.z; C[3] += v0.w;
        C[4] += v1.x; C[5] += v1.y; C[6] += v1.z; C[7] += v1.w;
        C[8] += v2.x;
    }

    // colsum: 128 partials per site
    float cs = 0.f;
    {
        const float4* src = (const float4*)(g_colp + (size_t)i * 128);
#pragma unroll
        for (int p = 0; p < 32; p++) {
            float4 v = src[p];
            cs += v.x + v.y + v.z + v.w;
        }
    }

    float R[9], Lq[9], Ab[9];
    {
        const float4* r4 = (const float4*)(g_R + (size_t)i * 12);
        float4 v0 = r4[0], v1 = r4[1], v2 = r4[2];
        R[0] = v0.x; R[1] = v0.y; R[2] = v0.z; R[3] = v0.w;
        R[4] = v1.x; R[5] = v1.y; R[6] = v1.z; R[7] = v1.w;
        R[8] = v2.x;
        const float4* q4 = (const float4*)(g_Lq + (size_t)i * 12);
        v0 = q4[0]; v1 = q4[1]; v2 = q4[2];
        Lq[0] = v0.x; Lq[1] = v0.y; Lq[2] = v0.z; Lq[3] = v0.w;
        Lq[4] = v1.x; Lq[5] = v1.y; Lq[6] = v1.z; Lq[7] = v1.w;
        Lq[8] = v2.x;
        const float4* p4 = (const float4*)(g_Lp + (size_t)i * 12);
        v0 = p4[0]; v1 = p4[1]; v2 = p4[2];
        Ab[0] = v0.x + Lo[0]; Ab[1] = v0.y + Lo[1]; Ab[2] = v0.z + Lo[2];
        Ab[3] = v0.w + Lo[3]; Ab[4] = v1.x + Lo[4]; Ab[5] = v1.y + Lo[5];
        Ab[6] = v1.z + Lo[6]; Ab[7] = v1.w + Lo[7]; Ab[8] = v2.x + Lo[8];
    }

    float T[9], Min[9];
    mm3(R, C, T);
    mmT3(T, R, Min);

    float M[9];
#pragma unroll
    for (int k = 0; k < 9; k++) M[k] = Ab[k] + Min[k] + cs * Lq[k];

    float Ms[9];
#pragma unroll
    for (int r = 0; r < 3; r++)
#pragma unroll
        for (int cc = 0; cc < 3; cc++)
            Ms[r * 3 + cc] = 0.5f * (M[r * 3 + cc] + M[cc * 3 + r]);

#pragma unroll
    for (int k = 0; k < 9; k++)
        if (!isfinite(Ms[k])) Ms[k] = (k == 0 || k == 4 || k == 8) ? 1.0f : 0.0f;
    Ms[0] += 1e-4f; Ms[4] += 1e-4f; Ms[8] += 1e-4f;

    float Mi[9];
    inv3(Ms, Mi);

#pragma unroll
    for (int k = 0; k < 9; k++) {
        out[i * 9 + k] = Ms[k];
        out[NS * 9 + i * 9 + k] = Mi[k];
    }
}

extern "C" void kernel_launch(void* const* d_in, const int* in_sizes, int n_in,
                              void* d_out, int out_size) {
    const float* Sp = (const float*)d_in[0];
    const float* Sq = (const float*)d_in[1];
    const float* phi = (const float*)d_in[2];
    const float* beta = (const float*)d_in[3];
    const float* mu = (const float*)d_in[4];
    const float* W = (const float*)d_in[5];
    float* out = (float*)d_out;

    mega_kernel<<<1544, 256>>>(Sp, Sq, phi, mu, W, beta);
    final_kernel<<<64, 32>>>(out);
}

// round 8
// speedup vs baseline: 1.1096x; 1.0060x over previous
#include <cuda_runtime.h>
#include <math.h>

#define NS 2048

// ---- scratch (device globals) ----
__device__ float g_R[NS * 12];           // rotation (stride 12 for float4 reads)
__device__ float g_Lq[NS * 12];          // Lambda_q
__device__ float g_Lp[NS * 12];          // Lambda_p
__device__ float g_sm[8 * NS * 12];      // softmax partials [e][site][10 of 12]
__device__ float g_colp[NS * 128];       // colsum partials [j][rg]
__device__ float g_Cpart[8 * NS * 12];   // beta@S partials [chunk][row][9 of 12]

// ---- packed f32x2 helpers ----
typedef unsigned long long ull;
__device__ __forceinline__ ull pk2(float a, float b) {
    ull r; asm("mov.b64 %0, {%1,%2};" : "=l"(r) : "f"(a), "f"(b)); return r;
}
__device__ __forceinline__ void upk2(ull p, float& a, float& b) {
    asm("mov.b64 {%0,%1}, %2;" : "=f"(a), "=f"(b) : "l"(p));
}
__device__ __forceinline__ ull fma2(ull a, ull b, ull c) {
    ull r; asm("fma.rn.f32x2 %0, %1, %2, %3;" : "=l"(r) : "l"(a), "l"(b), "l"(c)); return r;
}
__device__ __forceinline__ ull mul2(ull a, ull b) {
    ull r; asm("mul.rn.f32x2 %0, %1, %2;" : "=l"(r) : "l"(a), "l"(b)); return r;
}
__device__ __forceinline__ ull add2(ull a, ull b) {
    ull r; asm("add.rn.f32x2 %0, %1, %2;" : "=l"(r) : "l"(a), "l"(b)); return r;
}
__device__ __forceinline__ float ex2f(float x) {
    float r; asm("ex2.approx.f32 %0, %1;" : "=f"(r) : "f"(x)); return r;
}

// ---- 3x3 helpers ----
__device__ __forceinline__ void inv3(const float* a, float* o) {
    float c00 = a[4] * a[8] - a[5] * a[7];
    float c01 = a[5] * a[6] - a[3] * a[8];
    float c02 = a[3] * a[7] - a[4] * a[6];
    float det = a[0] * c00 + a[1] * c01 + a[2] * c02;
    float id = 1.0f / det;
    o[0] = c00 * id;
    o[1] = (a[2] * a[7] - a[1] * a[8]) * id;
    o[2] = (a[1] * a[5] - a[2] * a[4]) * id;
    o[3] = c01 * id;
    o[4] = (a[0] * a[8] - a[2] * a[6]) * id;
    o[5] = (a[2] * a[3] - a[0] * a[5]) * id;
    o[6] = c02 * id;
    o[7] = (a[1] * a[6] - a[0] * a[7]) * id;
    o[8] = (a[0] * a[4] - a[1] * a[3]) * id;
}
__device__ __forceinline__ void mm3(const float* A, const float* B, float* O) {
#pragma unroll
    for (int r = 0; r < 3; r++)
#pragma unroll
        for (int c = 0; c < 3; c++)
            O[r * 3 + c] = A[r * 3 + 0] * B[0 + c] + A[r * 3 + 1] * B[3 + c] + A[r * 3 + 2] * B[6 + c];
}
__device__ __forceinline__ void mTm3(const float* A, const float* B, float* O) {
#pragma unroll
    for (int r = 0; r < 3; r++)
#pragma unroll
        for (int c = 0; c < 3; c++)
            O[r * 3 + c] = A[0 + r] * B[0 + c] + A[3 + r] * B[3 + c] + A[6 + r] * B[6 + c];
}
__device__ __forceinline__ void mmT3(const float* A, const float* B, float* O) {
#pragma unroll
    for (int r = 0; r < 3; r++)
#pragma unroll
        for (int c = 0; c < 3; c++)
            O[r * 3 + c] = A[r * 3 + 0] * B[c * 3 + 0] + A[r * 3 + 1] * B[c * 3 + 1] + A[r * 3 + 2] * B[c * 3 + 2];
}
__device__ __forceinline__ void rodrigues(float x, float y, float z, float* R) {
    float t2 = x * x + y * y + z * z;
    float A, B;
    if (t2 < 1e-12f) {
        A = 1.0f - t2 * (1.0f / 6.0f);
        B = 0.5f - t2 * (1.0f / 24.0f);
    } else {
        float t = sqrtf(t2);
        A = sinf(t) / t;
        B = (1.0f - cosf(t)) / t2;
    }
    R[0] = 1.0f - B * (y * y + z * z);
    R[1] = -A * z + B * x * y;
    R[2] = A * y + B * x * z;
    R[3] = A * z + B * x * y;
    R[4] = 1.0f - B * (x * x + z * z);
    R[5] = -A * x + B * y * z;
    R[6] = -A * y + B * x * z;
    R[7] = A * x + B * y * z;
    R[8] = 1.0f - B * (x * x + y * y);
}

// compute S = R^T inv(Sq+eps) R for one site
__device__ __forceinline__ void site_S(const float* __restrict__ Sq,
                                       const float* __restrict__ phi,
                                       int site, float* Smat) {
    float a[9], Lq[9];
#pragma unroll
    for (int k = 0; k < 9; k++) a[k] = Sq[site * 9 + k];
    a[0] += 1e-6f; a[4] += 1e-6f; a[8] += 1e-6f;
    inv3(a, Lq);
    float R[9];
    rodrigues(phi[site * 3 + 0], phi[site * 3 + 1], phi[site * 3 + 2], R);
    float T[9];
    mm3(Lq, R, T);
    mTm3(R, T, Smat);
}

// ==== MEGA kernel ====
// blocks 0..1023   : beta@S GEMM partials + colsum partials (local S)
// blocks 1024..1031: geometry for the final kernel (Lp, Lq, R)
// blocks 1032..2055: softmax partial stats (2 sites/warp, V/8 split)
__global__ void __launch_bounds__(256) mega_kernel(
    const float* __restrict__ Sp, const float* __restrict__ Sq,
    const float* __restrict__ phi, const float* __restrict__ mu,
    const float* __restrict__ W, const float* __restrict__ beta) {
    __shared__ float buf[4608];

    if (blockIdx.x < 1024) {
        // ---------------- GEMM + colsum partials ----------------
        const int t = blockIdx.x;
        const int chunk = t & 7;
        const int rg = t >> 3;
        const int j0 = chunk * 256;
        const int warp = threadIdx.x >> 5;
        const int lane = threadIdx.x & 31;
        const int row0 = rg * 16 + warp * 2;

        float* sS = buf;            // [9][264]
        float* scol = buf + 2400;   // [8][264]

        {
            float Smat[9];
            site_S(Sq, phi, j0 + threadIdx.x, Smat);
#pragma unroll
            for (int k = 0; k < 9; k++) sS[k * 264 + threadIdx.x] = Smat[k];
        }
        __syncthreads();

        const int jj = lane * 8;
        const float* b0p = beta + (size_t)row0 * NS + j0 + jj;
        const float* b1p = b0p + NS;
        ulonglong2 b0 = *(const ulonglong2*)b0p;
        ulonglong2 b0h = *(const ulonglong2*)(b0p + 4);
        ulonglong2 b1 = *(const ulonglong2*)b1p;
        ulonglong2 b1h = *(const ulonglong2*)(b1p + 4);

        float c[2][9];
#pragma unroll
        for (int k = 0; k < 9; k++) {
            ulonglong2 sa = *(const ulonglong2*)&sS[k * 264 + jj];
            ulonglong2 sb = *(const ulonglong2*)&sS[k * 264 + jj + 4];
            ull a0 = fma2(b0.x, sa.x, mul2(b0.y, sa.y));
            a0 = fma2(b0h.x, sb.x, a0);
            a0 = fma2(b0h.y, sb.y, a0);
            ull a1 = fma2(b1.x, sa.x, mul2(b1.y, sa.y));
            a1 = fma2(b1h.x, sb.x, a1);
            a1 = fma2(b1h.y, sb.y, a1);
            float lo, hi;
            upk2(a0, lo, hi);
            c[0][k] = lo + hi;
            upk2(a1, lo, hi);
            c[1][k] = lo + hi;
        }

        {
            ull c0 = add2(b0.x, b1.x);
            ull c1 = add2(b0.y, b1.y);
            ull c2 = add2(b0h.x, b1h.x);
            ull c3 = add2(b0h.y, b1h.y);
            float* dst = scol + warp * 264 + jj;
            float lo, hi;
            upk2(c0, lo, hi); dst[0] = lo; dst[1] = hi;
            upk2(c1, lo, hi); dst[2] = lo; dst[3] = hi;
            upk2(c2, lo, hi); dst[4] = lo; dst[5] = hi;
            upk2(c3, lo, hi); dst[6] = lo; dst[7] = hi;
        }

#pragma unroll
        for (int r = 0; r < 2; r++)
#pragma unroll
            for (int k = 0; k < 9; k++)
#pragma unroll
                for (int off = 16; off; off >>= 1)
                    c[r][k] += __shfl_xor_sync(~0u, c[r][k], off);

        if (lane < 2) {
            const int row = row0 + lane;
            float* dst = g_Cpart + ((size_t)chunk * NS + row) * 12;
#pragma unroll
            for (int k = 0; k < 9; k++) dst[k] = c[lane][k];
        }

        __syncthreads();
        {
            float s = 0.f;
#pragma unroll
            for (int w = 0; w < 8; w++) s += scol[w * 264 + threadIdx.x];
            g_colp[(size_t)(j0 + threadIdx.x) * 128 + rg] = s;
        }
        return;
    }

    if (blockIdx.x < 1032) {
        // ---------------- geometry ----------------
        const int site = (blockIdx.x - 1024) * 256 + threadIdx.x;
        float a[9], Lp[9], Lq[9];
#pragma unroll
        for (int k = 0; k < 9; k++) a[k] = Sp[site * 9 + k];
        a[0] += 1e-6f; a[4] += 1e-6f; a[8] += 1e-6f;
        inv3(a, Lp);
#pragma unroll
        for (int k = 0; k < 9; k++) a[k] = Sq[site * 9 + k];
        a[0] += 1e-6f; a[4] += 1e-6f; a[8] += 1e-6f;
        inv3(a, Lq);
        float R[9];
        rodrigues(phi[site * 3 + 0], phi[site * 3 + 1], phi[site * 3 + 2], R);
#pragma unroll
        for (int k = 0; k < 9; k++) {
            g_R[site * 12 + k] = R[k];
            g_Lq[site * 12 + k] = Lq[k];
            g_Lp[site * 12 + k] = Lp[k];
        }
        return;
    }

    // ---------------- softmax (V/8 split, 2 sites/warp) ----------------
    {
        const int b2 = blockIdx.x - 1032;
        const int e = b2 & 7;          // V-eighth
        const int sg = b2 >> 3;        // 0..127
        const int warp = threadIdx.x >> 5;
        const int lane = threadIdx.x & 31;
        const int siteA = sg * 16 + warp * 2;
        const int siteB = siteA + 1;

        float* sW0 = buf;
        float* sW1 = buf + 1024;
        float* sW2 = buf + 2048;
        for (int vv = threadIdx.x; vv < 1024; vv += 256) {
            const float* wp = W + (size_t)(e * 1024 + vv) * 3;
            sW0[vv] = wp[0];
            sW1[vv] = wp[1];
            sW2[vv] = wp[2];
        }
        __syncthreads();

        const float LOG2E = 1.4426950408889634f;
        const ull muA0 = pk2(mu[siteA * 3 + 0] * LOG2E, mu[siteA * 3 + 0] * LOG2E);
        const ull muA1 = pk2(mu[siteA * 3 + 1] * LOG2E, mu[siteA * 3 + 1] * LOG2E);
        const ull muA2 = pk2(mu[siteA * 3 + 2] * LOG2E, mu[siteA * 3 + 2] * LOG2E);
        const ull muB0 = pk2(mu[siteB * 3 + 0] * LOG2E, mu[siteB * 3 + 0] * LOG2E);
        const ull muB1 = pk2(mu[siteB * 3 + 1] * LOG2E, mu[siteB * 3 + 1] * LOG2E);
        const ull muB2 = pk2(mu[siteB * 3 + 2] * LOG2E, mu[siteB * 3 + 2] * LOG2E);

        ull aA[10], aB[10];
#pragma unroll
        for (int k = 0; k < 10; k++) { aA[k] = 0ull; aB[k] = 0ull; }

#pragma unroll 4
        for (int it = 0; it < 8; it++) {
            int v = it * 128 + lane * 4;
            ulonglong2 w0 = *(const ulonglong2*)&sW0[v];
            ulonglong2 w1 = *(const ulonglong2*)&sW1[v];
            ulonglong2 w2 = *(const ulonglong2*)&sW2[v];
#pragma unroll
            for (int h = 0; h < 2; h++) {
                ull w0p = h ? w0.y : w0.x;
                ull w1p = h ? w1.y : w1.x;
                ull w2p = h ? w2.y : w2.x;
                ull lA = fma2(muA0, w0p, fma2(muA1, w1p, mul2(muA2, w2p)));
                ull lB = fma2(muB0, w0p, fma2(muB1, w1p, mul2(muB2, w2p)));
                float x0, x1, y0, y1;
                upk2(lA, x0, x1);
                upk2(lB, y0, y1);
                ull eA = pk2(ex2f(x0), ex2f(x1));
                ull eB = pk2(ex2f(y0), ex2f(y1));
                ull t0, t1, t2;
                t0 = mul2(eA, w0p); t1 = mul2(eA, w1p); t2 = mul2(eA, w2p);
                aA[0] = add2(aA[0], eA);
                aA[1] = add2(aA[1], t0);
                aA[2] = add2(aA[2], t1);
                aA[3] = add2(aA[3], t2);
                aA[4] = fma2(t0, w0p, aA[4]);
                aA[5] = fma2(t0, w1p, aA[5]);
                aA[6] = fma2(t0, w2p, aA[6]);
                aA[7] = fma2(t1, w1p, aA[7]);
                aA[8] = fma2(t1, w2p, aA[8]);
                aA[9] = fma2(t2, w2p, aA[9]);
                t0 = mul2(eB, w0p); t1 = mul2(eB, w1p); t2 = mul2(eB, w2p);
                aB[0] = add2(aB[0], eB);
                aB[1] = add2(aB[1], t0);
                aB[2] = add2(aB[2], t1);
                aB[3] = add2(aB[3], t2);
                aB[4] = fma2(t0, w0p, aB[4]);
                aB[5] = fma2(t0, w1p, aB[5]);
                aB[6] = fma2(t0, w2p, aB[6]);
                aB[7] = fma2(t1, w1p, aB[7]);
                aB[8] = fma2(t1, w2p, aB[8]);
                aB[9] = fma2(t2, w2p, aB[9]);
            }
        }

        float st[20];
#pragma unroll
        for (int k = 0; k < 10; k++) {
            float lo, hi;
            upk2(aA[k], lo, hi);
            st[k] = lo + hi;
            upk2(aB[k], lo, hi);
            st[10 + k] = lo + hi;
        }
#pragma unroll
        for (int k = 0; k < 20; k++)
#pragma unroll
            for (int off = 16; off; off >>= 1)
                st[k] += __shfl_xor_sync(~0u, st[k], off);

        if (lane < 2) {
            float* dst = g_sm + ((size_t)e * NS + siteA + lane) * 12;
#pragma unroll
            for (int k = 0; k < 10; k++) dst[k] = st[lane * 10 + k];
        }
    }
}

// ==== FINAL: 4 threads/site cooperative reduction, assemble M, invert ====
__global__ void __launch_bounds__(256) final_kernel(float* __restrict__ out) {
    const int i = blockIdx.x * 64 + (threadIdx.x >> 2);
    const int sub = threadIdx.x & 3;

    // softmax stats: 2 of 8 partials per sub-lane
    float st[10];
#pragma unroll
    for (int k = 0; k < 10; k++) st[k] = 0.f;
#pragma unroll
    for (int pp = 0; pp < 2; pp++) {
        int p = sub + pp * 4;
        const float4* src = (const float4*)(g_sm + ((size_t)p * NS + i) * 12);
        float4 v0 = src[0], v1 = src[1], v2 = src[2];
        st[0] += v0.x; st[1] += v0.y; st[2] += v0.z; st[3] += v0.w;
        st[4] += v1.x; st[5] += v1.y; st[6] += v1.z; st[7] += v1.w;
        st[8] += v2.x; st[9] += v2.y;
    }

    // C: 2 of 8 chunks per sub-lane
    float C[9];
#pragma unroll
    for (int k = 0; k < 9; k++) C[k] = 0.f;
#pragma unroll
    for (int pp = 0; pp < 2; pp++) {
        int p = sub * 2 + pp;
        const float4* src = (const float4*)(g_Cpart + ((size_t)p * NS + i) * 12);
        float4 v0 = src[0], v1 = src[1], v2 = src[2];
        C[0] += v0.x; C[1] += v0.y; C[2] += v0.z; C[3] += v0.w;
        C[4] += v1.x; C[5] += v1.y; C[6] += v1.z; C[7] += v1.w;
        C[8] += v2.x;
    }

    // colsum: 8 of 32 float4s per sub-lane
    float cs = 0.f;
    {
        const float4* src = (const float4*)(g_colp + (size_t)i * 128) + sub * 8;
#pragma unroll
        for (int p = 0; p < 8; p++) {
            float4 v = src[p];
            cs += v.x + v.y + v.z + v.w;
        }
    }

    // combine across the 4 sub-lanes (xor 1, 2 stay within aligned group)
#pragma unroll
    for (int off = 1; off <= 2; off <<= 1) {
#pragma unroll
        for (int k = 0; k < 10; k++) st[k] += __shfl_xor_sync(~0u, st[k], off);
#pragma unroll
        for (int k = 0; k < 9; k++) C[k] += __shfl_xor_sync(~0u, C[k], off);
        cs += __shfl_xor_sync(~0u, cs, off);
    }

    if (sub == 0) {
        float Zi = 1.0f / st[0];
        float m0 = st[1] * Zi, m1 = st[2] * Zi, m2 = st[3] * Zi;
        float Lo[9];
        Lo[0] = st[4] * Zi - m0 * m0 + 1e-6f;
        Lo[1] = st[5] * Zi - m0 * m1;
        Lo[2] = st[6] * Zi - m0 * m2;
        Lo[3] = Lo[1];
        Lo[4] = st[7] * Zi - m1 * m1 + 1e-6f;
        Lo[5] = st[8] * Zi - m1 * m2;
        Lo[6] = Lo[2];
        Lo[7] = Lo[5];
        Lo[8] = st[9] * Zi - m2 * m2 + 1e-6f;

        float R[9], Lq[9], Ab[9];
        {
            const float4* r4 = (const float4*)(g_R + (size_t)i * 12);
            float4 v0 = r4[0], v1 = r4[1], v2 = r4[2];
            R[0] = v0.x; R[1] = v0.y; R[2] = v0.z; R[3] = v0.w;
            R[4] = v1.x; R[5] = v1.y; R[6] = v1.z; R[7] = v1.w;
            R[8] = v2.x;
            const float4* q4 = (const float4*)(g_Lq + (size_t)i * 12);
            v0 = q4[0]; v1 = q4[1]; v2 = q4[2];
            Lq[0] = v0.x; Lq[1] = v0.y; Lq[2] = v0.z; Lq[3] = v0.w;
            Lq[4] = v1.x; Lq[5] = v1.y; Lq[6] = v1.z; Lq[7] = v1.w;
            Lq[8] = v2.x;
            const float4* p4 = (const float4*)(g_Lp + (size_t)i * 12);
            v0 = p4[0]; v1 = p4[1]; v2 = p4[2];
            Ab[0] = v0.x + Lo[0]; Ab[1] = v0.y + Lo[1]; Ab[2] = v0.z + Lo[2];
            Ab[3] = v0.w + Lo[3]; Ab[4] = v1.x + Lo[4]; Ab[5] = v1.y + Lo[5];
            Ab[6] = v1.z + Lo[6]; Ab[7] = v1.w + Lo[7]; Ab[8] = v2.x + Lo[8];
        }

        float T[9], Min[9];
        mm3(R, C, T);
        mmT3(T, R, Min);

        float M[9];
#pragma unroll
        for (int k = 0; k < 9; k++) M[k] = Ab[k] + Min[k] + cs * Lq[k];

        float Ms[9];
#pragma unroll
        for (int r = 0; r < 3; r++)
#pragma unroll
            for (int cc = 0; cc < 3; cc++)
                Ms[r * 3 + cc] = 0.5f * (M[r * 3 + cc] + M[cc * 3 + r]);

#pragma unroll
        for (int k = 0; k < 9; k++)
            if (!isfinite(Ms[k])) Ms[k] = (k == 0 || k == 4 || k == 8) ? 1.0f : 0.0f;
        Ms[0] += 1e-4f; Ms[4] += 1e-4f; Ms[8] += 1e-4f;

        float Mi[9];
        inv3(Ms, Mi);

#pragma unroll
        for (int k = 0; k < 9; k++) {
            out[i * 9 + k] = Ms[k];
            out[NS * 9 + i * 9 + k] = Mi[k];
        }
    }
}

extern "C" void kernel_launch(void* const* d_in, const int* in_sizes, int n_in,
                              void* d_out, int out_size) {
    const float* Sp = (const float*)d_in[0];
    const float* Sq = (const float*)d_in[1];
    const float* phi = (const float*)d_in[2];
    const float* beta = (const float*)d_in[3];
    const float* mu = (const float*)d_in[4];
    const float* W = (const float*)d_in[5];
    float* out = (float*)d_out;

    mega_kernel<<<2056, 256>>>(Sp, Sq, phi, mu, W, beta);
    final_kernel<<<32, 256>>>(out);
}